// round 4
// baseline (speedup 1.0000x reference)
#include <cuda_runtime.h>
#include <math.h>

#define NB 128
#define LXD 512
#define DD 32
#define KK 63
#define FF 2016   // KK*DD

// W3 transposed + b3 appended: row f = [W3[0][f]..W3[62][f], b3[f]]
__device__ float g_W3T[FF * 64];

__global__ void transpose_w3(const float* __restrict__ W3, const float* __restrict__ b3) {
    int idx = blockIdx.x * blockDim.x + threadIdx.x;
    if (idx >= FF * 64) return;
    int f = idx % FF;        // fastest -> coalesced reads of W3 row j
    int j = idx / FF;        // 0..63
    float v = (j < KK) ? W3[j * FF + f] : b3[f];
    g_W3T[f * 64 + j] = v;
}

// SMEM layout (floats)
#define OFF_X   0          // [512][33]  = 16896
#define OFF_H   16896      // [512][65]  = 33280
#define OFF_W   50176      // [64][65]   = 4160 (also W1s[32][64], W2s[63][64])
#define OFF_M   54336      // [512]
#define OFF_R1  54848      // [16][64]
#define OFF_R2  55872      // [16][64]
#define OFF_CM  56896      // [64]
#define OFF_OS  56960      // [64]
#define OFF_B1  57024      // [64]
#define OFF_B2  57088      // [64]
#define SMEM_FLOATS 57152  // 228608 bytes <= 232448

__global__ __launch_bounds__(512, 1)
void ttcn_main(const float* __restrict__ Xg, const float* __restrict__ Mg,
               const float* __restrict__ W1g, const float* __restrict__ b1g,
               const float* __restrict__ W2g, const float* __restrict__ b2g,
               const float* __restrict__ Tb,  float* __restrict__ Og)
{
    extern __shared__ float sm[];
    float* Xs = sm + OFF_X;
    float* Hs = sm + OFF_H;
    float* Ws = sm + OFF_W;
    float* Ms = sm + OFF_M;
    float* R1 = sm + OFF_R1;
    float* R2 = sm + OFF_R2;
    float* CM = sm + OFF_CM;
    float* OS = sm + OFF_OS;
    float* B1 = sm + OFF_B1;
    float* B2 = sm + OFF_B2;

    const int n    = blockIdx.x;
    const int t    = threadIdx.x;
    const int g    = t & 7;       // feature sub-group (0..7)
    const int lt   = t >> 3;      // l-group (0..63), rows lt*8..lt*8+7
    const int warp = t >> 5;
    const int lane = t & 31;

    // ---------- stage inputs ----------
    {
        const float* X = Xg + (size_t)n * (LXD * DD);
        #pragma unroll 4
        for (int idx = t; idx < LXD * DD; idx += 512) {
            int l = idx >> 5, d = idx & 31;
            Xs[l * 33 + d] = X[idx];
        }
        Ms[t] = Mg[n * LXD + t];
        for (int idx = t; idx < 32 * 64; idx += 512) {
            int d = idx >> 6, j = idx & 63;
            Ws[idx] = (j < KK) ? W1g[d * KK + j] : 0.f;
        }
        if (t < 64) { B1[t] = (t < KK) ? b1g[t] : 0.f; OS[t] = 0.f; }
    }
    __syncthreads();

    // ---------- Phase A: H1 = relu(X @ W1 + b1) ----------
    {
        float acc[8][8];
        #pragma unroll
        for (int i = 0; i < 8; i++)
            #pragma unroll
            for (int fi = 0; fi < 8; fi++) acc[i][fi] = 0.f;

        const float* hp = &Xs[(lt * 8) * 33];
        const float* wp = &Ws[g];
        #pragma unroll 4
        for (int d = 0; d < 32; ++d) {
            float h[8], w[8];
            #pragma unroll
            for (int i = 0; i < 8; i++) h[i] = hp[i * 33 + d];
            #pragma unroll
            for (int fi = 0; fi < 8; fi++) w[fi] = wp[d * 64 + fi * 8];
            #pragma unroll
            for (int i = 0; i < 8; i++)
                #pragma unroll
                for (int fi = 0; fi < 8; fi++) acc[i][fi] += h[i] * w[fi];
        }
        __syncthreads();   // all W1s reads done before Ws is overwritten below
        #pragma unroll
        for (int fi = 0; fi < 8; fi++) {
            int j = fi * 8 + g;
            if (j < KK) {
                float bb = B1[j];
                #pragma unroll
                for (int i = 0; i < 8; i++)
                    Hs[(lt * 8 + i) * 65 + j] = fmaxf(acc[i][fi] + bb, 0.f);
            }
        }
        // load W2 into Ws (same region)
        for (int idx = t; idx < KK * 64; idx += 512) {
            int i2 = idx >> 6, j = idx & 63;
            Ws[idx] = (j < KK) ? W2g[i2 * KK + j] : 0.f;
        }
        if (t < 64) B2[t] = (t < KK) ? b2g[t] : 0.f;
    }
    __syncthreads();

    // ---------- Phase B: H2 = relu(H1 @ W2 + b2) ----------
    {
        float acc[8][8];
        #pragma unroll
        for (int i = 0; i < 8; i++)
            #pragma unroll
            for (int fi = 0; fi < 8; fi++) acc[i][fi] = 0.f;

        const float* hp = &Hs[(lt * 8) * 65];
        const float* wp = &Ws[g];
        #pragma unroll 3
        for (int i2 = 0; i2 < KK; ++i2) {
            float h[8], w[8];
            #pragma unroll
            for (int i = 0; i < 8; i++) h[i] = hp[i * 65 + i2];
            #pragma unroll
            for (int fi = 0; fi < 8; fi++) w[fi] = wp[i2 * 64 + fi * 8];
            #pragma unroll
            for (int i = 0; i < 8; i++)
                #pragma unroll
                for (int fi = 0; fi < 8; fi++) acc[i][fi] += h[i] * w[fi];
        }
        __syncthreads();   // all H1 reads complete before H2 overwrites rows
        #pragma unroll
        for (int fi = 0; fi < 8; fi++) {
            int j = fi * 8 + g;
            if (j < KK) {
                float bb = B2[j];
                #pragma unroll
                for (int i = 0; i < 8; i++)
                    Hs[(lt * 8 + i) * 65 + j] = fmaxf(acc[i][fi] + bb, 0.f);
            }
        }
    }
    __syncthreads();

    // ---------- Phase C: fused logits GEMM + masked softmax(Lx) + X-weighted pool ----------
    float mreg[8];
    #pragma unroll
    for (int i = 0; i < 8; i++) mreg[i] = Ms[lt * 8 + i];

    const float* hpC = &Hs[(lt * 8) * 65];
    const float* wpC = &Ws[g * 65];

    for (int r = 0; r < 32; ++r) {
        const int f_base = r * 64;

        // stage W3T tile [64 features][64] (63 weights + b3), zero-pad past FF
        for (int idx = t; idx < 64 * 64; idx += 512) {
            int fl = idx >> 6, jj = idx & 63;
            int f = f_base + fl;
            Ws[fl * 65 + jj] = (f < FF) ? g_W3T[f * 64 + jj] : 0.f;
        }
        __syncthreads();

        // z-tile: 8 rows (l) x 8 cols (f) per thread
        float acc[8][8];
        #pragma unroll
        for (int i = 0; i < 8; i++)
            #pragma unroll
            for (int fi = 0; fi < 8; fi++) acc[i][fi] = 0.f;

        #pragma unroll 3
        for (int j = 0; j < KK; ++j) {
            float h[8], w[8];
            #pragma unroll
            for (int i = 0; i < 8; i++) h[i] = hpC[i * 65 + j];
            #pragma unroll
            for (int fi = 0; fi < 8; fi++) w[fi] = wpC[fi * 520 + j];
            #pragma unroll
            for (int i = 0; i < 8; i++)
                #pragma unroll
                for (int fi = 0; fi < 8; fi++) acc[i][fi] += h[i] * w[fi];
        }
        float b3f[8];
        #pragma unroll
        for (int fi = 0; fi < 8; fi++) b3f[fi] = wpC[fi * 520 + 63];

        // mask + per-thread column max
        float lm[8];
        #pragma unroll
        for (int fi = 0; fi < 8; fi++) lm[fi] = -3.4e38f;
        #pragma unroll
        for (int i = 0; i < 8; i++) {
            bool um = mreg[i] > 0.5f;
            #pragma unroll
            for (int fi = 0; fi < 8; fi++) {
                float z = um ? (acc[i][fi] + b3f[fi]) : -1e8f;
                acc[i][fi] = z;
                lm[fi] = fmaxf(lm[fi], z);
            }
        }
        // reduce max over the 4 l-subgroups within the warp, then across warps
        #pragma unroll
        for (int fi = 0; fi < 8; fi++) {
            lm[fi] = fmaxf(lm[fi], __shfl_xor_sync(0xffffffffu, lm[fi], 8));
            lm[fi] = fmaxf(lm[fi], __shfl_xor_sync(0xffffffffu, lm[fi], 16));
        }
        if (lane < 8) {
            #pragma unroll
            for (int fi = 0; fi < 8; fi++) R1[warp * 64 + fi * 8 + g] = lm[fi];
        }
        __syncthreads();
        if (t < 64) {
            float m = -3.4e38f;
            #pragma unroll
            for (int w16 = 0; w16 < 16; w16++) m = fmaxf(m, R1[w16 * 64 + t]);
            CM[t] = m;
        }
        __syncthreads();

        float cm[8];
        #pragma unroll
        for (int fi = 0; fi < 8; fi++) cm[fi] = CM[fi * 8 + g];

        // exp + local partials of S (denominator) and A (X-weighted numerator)
        float Sp[8], Ap[8];
        #pragma unroll
        for (int fi = 0; fi < 8; fi++) { Sp[fi] = 0.f; Ap[fi] = 0.f; }
        #pragma unroll
        for (int i = 0; i < 8; i++) {
            float x4[4];
            #pragma unroll
            for (int q = 0; q < 4; q++) x4[q] = Xs[(lt * 8 + i) * 33 + g + 8 * q];
            #pragma unroll
            for (int fi = 0; fi < 8; fi++) {
                float e = __expf(acc[i][fi] - cm[fi]);
                Sp[fi] += e;
                Ap[fi] += e * x4[fi & 3];   // d = 8*(fi%4)+g
            }
        }
        #pragma unroll
        for (int fi = 0; fi < 8; fi++) {
            Sp[fi] += __shfl_xor_sync(0xffffffffu, Sp[fi], 8);
            Sp[fi] += __shfl_xor_sync(0xffffffffu, Sp[fi], 16);
            Ap[fi] += __shfl_xor_sync(0xffffffffu, Ap[fi], 8);
            Ap[fi] += __shfl_xor_sync(0xffffffffu, Ap[fi], 16);
        }
        if (lane < 8) {
            #pragma unroll
            for (int fi = 0; fi < 8; fi++) {
                R1[warp * 64 + fi * 8 + g] = Sp[fi];
                R2[warp * 64 + fi * 8 + g] = Ap[fi];
            }
        }
        __syncthreads();
        if (t < 64) {
            float S = 0.f, A = 0.f;
            #pragma unroll
            for (int w16 = 0; w16 < 16; w16++) {
                S += R1[w16 * 64 + t];
                A += R2[w16 * 64 + t];
            }
            int f = f_base + t;
            float gq = (f < FF) ? (A / S) : 0.f;
            // sum the 32 d-contributions of this k within the warp
            gq += __shfl_down_sync(0xffffffffu, gq, 16);
            gq += __shfl_down_sync(0xffffffffu, gq, 8);
            gq += __shfl_down_sync(0xffffffffu, gq, 4);
            gq += __shfl_down_sync(0xffffffffu, gq, 2);
            gq += __shfl_down_sync(0xffffffffu, gq, 1);
            if (lane == 0) OS[f >> 5] = gq;   // k = 2r + warp, each k written once
        }
        __syncthreads();
    }

    if (t < KK) Og[n * KK + t] = fmaxf(OS[t] + Tb[t], 0.f);
}

extern "C" void kernel_launch(void* const* d_in, const int* in_sizes, int n_in,
                              void* d_out, int out_size) {
    const float* X  = (const float*)d_in[0];
    const float* M  = (const float*)d_in[1];
    const float* W1 = (const float*)d_in[2];
    const float* b1 = (const float*)d_in[3];
    const float* W2 = (const float*)d_in[4];
    const float* b2 = (const float*)d_in[5];
    const float* W3 = (const float*)d_in[6];
    const float* b3 = (const float*)d_in[7];
    const float* Tb = (const float*)d_in[8];
    float* Og = (float*)d_out;

    transpose_w3<<<(FF * 64 + 255) / 256, 256>>>(W3, b3);

    size_t smem = (size_t)SMEM_FLOATS * sizeof(float);
    cudaFuncSetAttribute(ttcn_main, cudaFuncAttributeMaxDynamicSharedMemorySize, (int)smem);
    ttcn_main<<<NB, 512, smem>>>(X, M, W1, b1, W2, b2, Tb, Og);
}